// round 17
// baseline (speedup 1.0000x reference)
#include <cuda_runtime.h>
#include <math.h>
#include <stddef.h>

#define NN     4096
#define TT     16
#define FF     4
#define HIDC   64
#define NH     4
#define NCHUNK 512
#define CHSZ   8
#define CHLOG  3
#define NSUPER 32
#define SUPSZ  16
#define SUPLOG 4

// ---------------------------------------------------------------------------
// Scratch
// ---------------------------------------------------------------------------
struct __align__(16) Scratch {
    float  Wh[NH * NN * HIDC];
    float  s1[NH * NN];
    float  s2[NH * NN];
    float  s2s[NH * NN];
    float  s2c[NH * 64];               // coarse table: s2s[64j]
    int    perm[NH * NN];
    float  A[NH * NN];
    float  B[NH * NN];
    float  csA[NH * NCHUNK * HIDC];    // within-super exclusive suffix
    float  csB[NH * NCHUNK * HIDC];    // within-super exclusive prefix
    float  ssA[NH * NSUPER * HIDC];    // super totals -> exclusive suffix
    float  ssB[NH * NSUPER * HIDC];
    double sufAsc[NH * (NN + 1)];
    double preBsc[NH * (NN + 1)];
    // layer 2
    float  Wh2[NN * TT];
    float  s1o[NN], s2o[NN], s2so[NN];
    float  s2co[64];
    int    permo[NN];
    float  Ao[NN], Bo[NN];
    float  csA2[NCHUNK * TT], csB2[NCHUNK * TT];
    float  ssA2[NSUPER * TT], ssB2[NSUPER * TT];
    double sufA2sc[NN + 1], preB2sc[NN + 1];
};
__device__ Scratch S;

__device__ unsigned int g_ctr;   // monotonic epoch counter (never reset)

// ---------------------------------------------------------------------------
// Kernel 1: fused transpose(x) -> h, Wh = h @ W[head], s1/s2 dots
// grid (NN/64, NH), block 256
// ---------------------------------------------------------------------------
__global__ void k_gemm1(const float* __restrict__ x,
                        const float* __restrict__ W,
                        const float* __restrict__ a1,
                        const float* __restrict__ a2)
{
    __shared__ float sW[64 * 65];
    __shared__ float sh[64 * 65];

    const int head = blockIdx.y;
    const int n0   = blockIdx.x * 64;
    const int t    = threadIdx.x;

    const float* Wp = W + head * 64 * 64;
    for (int idx = t; idx < 4096; idx += 256)
        sW[(idx >> 6) * 65 + (idx & 63)] = Wp[idx];

    {
        const int dn = t >> 2, f = t & 3;
        #pragma unroll
        for (int tt = 0; tt < TT; tt++)
            sh[dn * 65 + tt * 4 + f] = x[(size_t)tt * NN * FF + (size_t)(n0 + dn) * FF + f];
    }
    __syncthreads();

    const int tc = t & 15, tr = t >> 4;
    float acc[4][4];
    #pragma unroll
    for (int i = 0; i < 4; i++)
        #pragma unroll
        for (int j = 0; j < 4; j++) acc[i][j] = 0.f;

    for (int k = 0; k < 64; k++) {
        float av[4], bv[4];
        #pragma unroll
        for (int i = 0; i < 4; i++) av[i] = sh[(tr + 16 * i) * 65 + k];
        #pragma unroll
        for (int j = 0; j < 4; j++) bv[j] = sW[k * 65 + tc + 16 * j];
        #pragma unroll
        for (int i = 0; i < 4; i++)
            #pragma unroll
            for (int j = 0; j < 4; j++) acc[i][j] = fmaf(av[i], bv[j], acc[i][j]);
    }
    __syncthreads();

    float* __restrict__ WhG = S.Wh;
    #pragma unroll
    for (int i = 0; i < 4; i++) {
        const int r = tr + 16 * i;
        #pragma unroll
        for (int j = 0; j < 4; j++) {
            const int c = tc + 16 * j;
            sW[r * 65 + c] = acc[i][j];
            WhG[((size_t)head * NN + (n0 + r)) * HIDC + c] = acc[i][j];
        }
    }
    __syncthreads();

    if (t < 64) {
        const int r = t;
        const float* ap1 = a1 + head * HIDC;
        const float* ap2 = a2 + head * HIDC;
        float v1 = 0.f, v2 = 0.f;
        #pragma unroll
        for (int c = 0; c < 64; c++) {
            const float w = sW[r * 65 + c];
            v1 = fmaf(w, ap1[c], v1);
            v2 = fmaf(w, ap2[c], v2);
        }
        S.s1[head * NN + n0 + r] = v1;
        S.s2[head * NN + n0 + r] = v2;
    }
}

// ---------------------------------------------------------------------------
// Device body: bitonic sort + exp weights + coarse table + fp64 scalar scans.
// ---------------------------------------------------------------------------
__device__ void sort_scan_body(const float* __restrict__ s2,
                               float* __restrict__ s2s,
                               float* __restrict__ s2c,
                               int*   __restrict__ perm,
                               float* __restrict__ A,
                               float* __restrict__ B,
                               double* __restrict__ sufAsc,
                               double* __restrict__ preBsc,
                               float* key, int* sidx)
{
    const int t    = threadIdx.x;
    const int lane = t & 31;

    float k0[4]; int x0[4];
    #pragma unroll
    for (int m = 0; m < 4; m++) {
        const int i = t + m * 1024;
        k0[m] = s2[i];
        x0[m] = i;
    }

    #pragma unroll
    for (int k = 2; k <= 32; k <<= 1) {
        #pragma unroll
        for (int j = k >> 1; j >= 1; j >>= 1) {
            #pragma unroll
            for (int m = 0; m < 4; m++) {
                const int i = t + m * 1024;
                const bool up = ((i & k) == 0);
                const float ok = __shfl_xor_sync(0xffffffffu, k0[m], j);
                const int   oi = __shfl_xor_sync(0xffffffffu, x0[m], j);
                const bool lower = ((lane & j) == 0);
                const bool wantMin = (lower == up);
                const bool take = wantMin ? (ok < k0[m]) : (ok > k0[m]);
                if (take) { k0[m] = ok; x0[m] = oi; }
            }
        }
    }
    #pragma unroll
    for (int m = 0; m < 4; m++) {
        const int i = t + m * 1024;
        key[i] = k0[m]; sidx[i] = x0[m];
    }
    __syncthreads();

    for (int k = 64; k <= NN; k <<= 1) {
        for (int j = k >> 1; j >= 32; j >>= 1) {
            #pragma unroll
            for (int m = 0; m < 4; m++) {
                const int i = t + m * 1024;
                const int ixj = i ^ j;
                if (ixj > i) {
                    const bool up = ((i & k) == 0);
                    const float a = key[i], b = key[ixj];
                    if ((a > b) == up) {
                        key[i] = b; key[ixj] = a;
                        const int tmp = sidx[i]; sidx[i] = sidx[ixj]; sidx[ixj] = tmp;
                    }
                }
            }
            __syncthreads();
        }
        #pragma unroll
        for (int m = 0; m < 4; m++) {
            const int i = t + m * 1024;
            k0[m] = key[i]; x0[m] = sidx[i];
        }
        #pragma unroll
        for (int j = 16; j >= 1; j >>= 1) {
            #pragma unroll
            for (int m = 0; m < 4; m++) {
                const int i = t + m * 1024;
                const bool up = ((i & k) == 0);
                const float ok = __shfl_xor_sync(0xffffffffu, k0[m], j);
                const int   oi = __shfl_xor_sync(0xffffffffu, x0[m], j);
                const bool lower = ((lane & j) == 0);
                const bool wantMin = (lower == up);
                const bool take = wantMin ? (ok < k0[m]) : (ok > k0[m]);
                if (take) { k0[m] = ok; x0[m] = oi; }
            }
        }
        #pragma unroll
        for (int m = 0; m < 4; m++) {
            const int i = t + m * 1024;
            key[i] = k0[m]; sidx[i] = x0[m];
        }
        __syncthreads();
    }

    #pragma unroll
    for (int m = 0; m < 4; m++) {
        const int i = t + m * 1024;
        const float v = k0[m];
        s2s[i]  = v;
        perm[i] = x0[m];
        A[i]    = expf(v);
        B[i]    = expf(0.01f * v);
        if ((i & 63) == 0) s2c[i >> 6] = v;
    }
    __syncthreads();

    // scalar fp64 scans
    double* seg = (double*)sidx;
    float av[4], bv[4];
    double la = 0.0, lb = 0.0;
    #pragma unroll
    for (int e = 0; e < 4; e++) {
        const float v = key[4 * t + e];
        av[e] = expf(v); bv[e] = expf(0.01f * v);
        la += (double)av[e]; lb += (double)bv[e];
    }
    seg[t] = la; seg[1024 + t] = lb;
    __syncthreads();

    for (int d = 1; d < 1024; d <<= 1) {
        double va = 0.0, vb = 0.0;
        if (t >= d) { va = seg[t - d]; vb = seg[1024 + t - d]; }
        __syncthreads();
        seg[t] += va; seg[1024 + t] += vb;
        __syncthreads();
    }

    const double exA = seg[t] - la;
    const double exB = seg[1024 + t] - lb;
    const double totA = seg[1023];
    const double totB = seg[2047];

    double runB = exB, runA = exA;
    #pragma unroll
    for (int e = 0; e < 4; e++) {
        const int p = 4 * t + e;
        preBsc[p] = runB;        runB += (double)bv[e];
        sufAsc[p] = totA - runA; runA += (double)av[e];
    }
    if (t == 1023) { preBsc[NN] = totB; sufAsc[NN] = 0.0; }
    __syncthreads();
}

// ---------------------------------------------------------------------------
// Kernel 2: sortscan L0 wrapper — 1 block of 1024 per head
// ---------------------------------------------------------------------------
__global__ void __launch_bounds__(1024, 1) k_sortscan0()
{
    __shared__ float key[NN];
    __shared__ int   sidx[NN];
    const int head = blockIdx.x;
    sort_scan_body(S.s2 + head * NN, S.s2s + head * NN, S.s2c + head * 64,
                   S.perm + head * NN, S.A + head * NN, S.B + head * NN,
                   S.sufAsc + head * (NN + 1), S.preBsc + head * (NN + 1),
                   key, sidx);
}

// ---------------------------------------------------------------------------
// Kernel 3: chunk sums + within-super scans; LAST block does super-total scan.
// grid (NH, NSUPER) = 128 blocks, block 1024.
// ---------------------------------------------------------------------------
__global__ void __launch_bounds__(1024, 1) k_chunksum0()
{
    __shared__ float sA[SUPSZ][HIDC + 1];
    __shared__ float sB[SUPSZ][HIDC + 1];
    __shared__ int   sLast;

    const int head = blockIdx.x;
    const int sq   = blockIdx.y;
    const float* __restrict__ Wh   = S.Wh   + (size_t)head * NN * HIDC;
    const int*   __restrict__ perm = S.perm + head * NN;
    const float* __restrict__ A    = S.A    + head * NN;
    const float* __restrict__ B    = S.B    + head * NN;
    float*       __restrict__ csA  = S.csA  + (size_t)head * NCHUNK * HIDC;
    float*       __restrict__ csB  = S.csB  + (size_t)head * NCHUNK * HIDC;

    const int t  = threadIdx.x;
    const int ql = t >> 6;          // 0..15
    const int c  = t & 63;

    {
        const int q  = sq * SUPSZ + ql;
        const int p0 = q * CHSZ;
        float sa = 0.f, sb = 0.f;
        #pragma unroll
        for (int e = 0; e < CHSZ; e++) {
            const int p = p0 + e;
            const float w = Wh[(size_t)perm[p] * HIDC + c];
            sa = fmaf(A[p], w, sa);
            sb = fmaf(B[p], w, sb);
        }
        sA[ql][c] = sa;
        sB[ql][c] = sb;
    }
    __syncthreads();

    if (t < HIDC) {
        const int cc = t;
        float run = 0.f;
        #pragma unroll
        for (int j = SUPSZ - 1; j >= 0; j--) {
            const float v = sA[j][cc];
            csA[(sq * SUPSZ + j) * HIDC + cc] = run;
            run += v;
        }
        S.ssA[(size_t)head * NSUPER * HIDC + sq * HIDC + cc] = run;
    } else if (t < 2 * HIDC) {
        const int cc = t - HIDC;
        float run = 0.f;
        #pragma unroll
        for (int j = 0; j < SUPSZ; j++) {
            const float v = sB[j][cc];
            csB[(sq * SUPSZ + j) * HIDC + cc] = run;
            run += v;
        }
        S.ssB[(size_t)head * NSUPER * HIDC + sq * HIDC + cc] = run;
    }

    __threadfence();
    __syncthreads();
    if (t == 0) {
        const unsigned v = atomicAdd(&g_ctr, 1u);
        sLast = (((v + 1u) & 127u) == 0u) ? 1 : 0;
    }
    __syncthreads();
    if (sLast) {
        __threadfence();
        if (t < NH * HIDC) {
            const int h2 = t >> 6, cc = t & 63;
            float* base = S.ssA + (size_t)h2 * NSUPER * HIDC + cc;
            float v[NSUPER];
            #pragma unroll
            for (int i = 0; i < NSUPER; i++) v[i] = base[i * HIDC];
            float run = 0.f;
            #pragma unroll
            for (int i = NSUPER - 1; i >= 0; i--) { const float tv = v[i]; base[i * HIDC] = run; run += tv; }
        } else if (t < 2 * NH * HIDC) {
            const int u = t - NH * HIDC;
            const int h2 = u >> 6, cc = u & 63;
            float* base = S.ssB + (size_t)h2 * NSUPER * HIDC + cc;
            float v[NSUPER];
            #pragma unroll
            for (int i = 0; i < NSUPER; i++) v[i] = base[i * HIDC];
            float run = 0.f;
            #pragma unroll
            for (int i = 0; i < NSUPER; i++) { const float tv = v[i]; base[i * HIDC] = run; run += tv; }
        }
    }
}

// ---------------------------------------------------------------------------
// Kernel 4 (FUSED): combine L0 + gemm2 + s1o/s2o.
// grid NN/4 = 1024 blocks, block 256 = 4 rows x (4 heads x 16 lanes).
// Phase A: combine (hcat row -> smem, never global).
// Phase B: Wh2 tile = hc @ Wo (Wo staged in smem), s1o/s2o dots.
// ---------------------------------------------------------------------------
__global__ void __launch_bounds__(256) k_combine0_gemm2(
    const float* __restrict__ Wo,
    const float* __restrict__ a1o,
    const float* __restrict__ a2o)
{
    __shared__ float sWo[256 * 17];        // Wo [k][c] padded
    __shared__ float hc[4 * 256];          // hcat rows (4 x 256)
    __shared__ float part[4][16][4];
    __shared__ float wrow[4][17];
    __shared__ float  sEa[4][NH], sEb[4][NH], sWii[4][NH];
    __shared__ double sRd[4][NH];
    __shared__ float  sCoef[4][NH][CHSZ];
    __shared__ int    sOff[4][NH][CHSZ];
    __shared__ int    sQ[4][NH];

    const int t    = threadIdx.x;
    const int r    = t >> 6;            // 0..3 row in block
    const int l64  = t & 63;
    const int head = l64 >> 4;
    const int lane = l64 & 15;
    const int c4   = lane * 4;
    const int i    = blockIdx.x * 4 + r;

    // stage Wo (used in phase B)
    for (int idx = t; idx < 4096; idx += 256)
        sWo[(idx >> 4) * 17 + (idx & 15)] = Wo[idx];

    // head-specific pointers
    const float*  __restrict__ s1     = S.s1  + head * NN;
    const float*  __restrict__ s2     = S.s2  + head * NN;
    const float*  __restrict__ s2s    = S.s2s + head * NN;
    const float*  __restrict__ s2c    = S.s2c + head * 64;
    const int*    __restrict__ perm   = S.perm + head * NN;
    const float*  __restrict__ A      = S.A + head * NN;
    const float*  __restrict__ B      = S.B + head * NN;
    const float*  __restrict__ Wh     = S.Wh  + (size_t)head * NN * HIDC;
    const float*  __restrict__ csAs   = S.csA + (size_t)head * NCHUNK * HIDC;
    const float*  __restrict__ csBs   = S.csB + (size_t)head * NCHUNK * HIDC;
    const float*  __restrict__ ssAs   = S.ssA + (size_t)head * NSUPER * HIDC;
    const float*  __restrict__ ssBs   = S.ssB + (size_t)head * NSUPER * HIDC;
    const double* __restrict__ sufAsc = S.sufAsc + head * (NN + 1);
    const double* __restrict__ preBsc = S.preBsc + head * (NN + 1);

    if (lane == 0) {
        const float s1v = s1[i];
        const float ea  = expf(s1v);
        const float eb  = expf(0.01f * s1v);
        const float target = -s1v;
        int lo = 0, hi = 64;
        while (lo < hi) {
            const int mid = (lo + hi) >> 1;
            if (s2c[mid] < target) lo = mid + 1; else hi = mid;
        }
        const int co = lo;
        int l2, h2;
        if (co == 0) { l2 = 0; h2 = 0; }
        else { l2 = 64 * (co - 1) + 1; h2 = (co == 64) ? NN : 64 * co; }
        while (l2 < h2) {
            const int mid = (l2 + h2) >> 1;
            if (s2s[mid] < target) l2 = mid + 1; else h2 = mid;
        }
        const int k = l2;
        const int q = min(k >> CHLOG, NCHUNK - 1);
        const int p0 = q << CHLOG;
        #pragma unroll
        for (int e = 0; e < CHSZ; e++) {
            const int p = p0 + e;
            sCoef[r][head][e] = (p >= k) ? ea * A[p] : eb * B[p];
            sOff[r][head][e]  = perm[p] * HIDC;
        }
        const float tii = s1v + s2[i];
        const float wii = expf(tii >= 0.f ? tii : 0.01f * tii);
        const double denom = (double)ea * sufAsc[k] + (double)eb * preBsc[k] - (double)wii;
        sEa[r][head] = ea;  sEb[r][head] = eb;  sWii[r][head] = wii;
        sQ[r][head] = q;
        sRd[r][head] = 1.0 / denom;
    }
    __syncthreads();

    // Phase A workers: compute 4 channels, write to smem hc
    {
        const float  ea  = sEa[r][head];
        const float  eb  = sEb[r][head];
        const float  wii = sWii[r][head];
        const double rd  = sRd[r][head];
        const int    q   = sQ[r][head];
        const int    sq  = q >> SUPLOG;

        const float4 cA = *(const float4*)(csAs + q * HIDC + c4);
        const float4 sAv= *(const float4*)(ssAs + sq * HIDC + c4);
        const float4 cB = *(const float4*)(csBs + q * HIDC + c4);
        const float4 sBv= *(const float4*)(ssBs + sq * HIDC + c4);

        float a0  = ea * (cA.x + sAv.x) + eb * (cB.x + sBv.x);
        float a1_ = ea * (cA.y + sAv.y) + eb * (cB.y + sBv.y);
        float a2_ = ea * (cA.z + sAv.z) + eb * (cB.z + sBv.z);
        float a3  = ea * (cA.w + sAv.w) + eb * (cB.w + sBv.w);

        #pragma unroll
        for (int e = 0; e < CHSZ; e++) {
            const float cf = sCoef[r][head][e];
            const float4 w4 = *(const float4*)(Wh + (size_t)sOff[r][head][e] + c4);
            a0  = fmaf(cf, w4.x, a0);
            a1_ = fmaf(cf, w4.y, a1_);
            a2_ = fmaf(cf, w4.z, a2_);
            a3  = fmaf(cf, w4.w, a3);
        }

        const float4 wd = *(const float4*)(Wh + (size_t)i * HIDC + c4);
        float v0 = (float)((double)(a0  - wii * wd.x) * rd);
        float v1 = (float)((double)(a1_ - wii * wd.y) * rd);
        float v2 = (float)((double)(a2_ - wii * wd.z) * rd);
        float v3 = (float)((double)(a3  - wii * wd.w) * rd);
        v0 = (v0 > 0.f) ? v0 : expm1f(v0);
        v1 = (v1 > 0.f) ? v1 : expm1f(v1);
        v2 = (v2 > 0.f) ? v2 : expm1f(v2);
        v3 = (v3 > 0.f) ? v3 : expm1f(v3);
        *(float4*)(hc + r * 256 + head * HIDC + c4) = make_float4(v0, v1, v2, v3);
    }
    __syncthreads();

    // Phase B: Wh2[4 x 16] = hc @ Wo, 4-way k-split
    {
        const int r2 = t >> 6, c = (t >> 2) & 15, seg = t & 3;
        const float* hr = hc + r2 * 256 + seg * 64;
        float p = 0.f;
        #pragma unroll 16
        for (int k = 0; k < 64; k++)
            p = fmaf(hr[k], sWo[(seg * 64 + k) * 17 + c], p);
        part[r2][c][seg] = p;
    }
    __syncthreads();

    if (t < 64) {
        const int r2 = t >> 4, c = t & 15;
        const float v = part[r2][c][0] + part[r2][c][1] + part[r2][c][2] + part[r2][c][3];
        S.Wh2[(blockIdx.x * 4 + r2) * TT + c] = v;
        wrow[r2][c] = v;
    }
    __syncthreads();

    if (t < 4) {
        const int r2 = t;
        float v1 = 0.f, v2 = 0.f;
        #pragma unroll
        for (int c = 0; c < 16; c++) {
            const float w = wrow[r2][c];
            v1 = fmaf(w, a1o[c], v1);
            v2 = fmaf(w, a2o[c], v2);
        }
        S.s1o[blockIdx.x * 4 + r2] = v1;
        S.s2o[blockIdx.x * 4 + r2] = v2;
    }
}

// ---------------------------------------------------------------------------
// Kernel 5: per-row combine L1, float4 workers (4 channels/thread).
// ---------------------------------------------------------------------------
template<int C, bool DO_ELU>
__global__ void k_combine1(float* __restrict__ out, int rowStride)
{
    constexpr int LPR = C / 4;
    constexpr int IPB = 256 / LPR;
    __shared__ float  sEa[IPB], sEb[IPB], sWii[IPB];
    __shared__ double sRd[IPB];
    __shared__ float  sCoef[IPB][CHSZ];
    __shared__ int    sOff[IPB][CHSZ];
    __shared__ int    sQ[IPB];

    const float*  __restrict__ s1     = S.s1o;
    const float*  __restrict__ s2     = S.s2o;
    const float*  __restrict__ s2s    = S.s2so;
    const float*  __restrict__ s2c    = S.s2co;
    const int*    __restrict__ perm   = S.permo;
    const float*  __restrict__ A      = S.Ao;
    const float*  __restrict__ B      = S.Bo;
    const float*  __restrict__ Wh     = S.Wh2;
    const float*  __restrict__ csAs   = S.csA2;
    const float*  __restrict__ csBs   = S.csB2;
    const float*  __restrict__ ssAs   = S.ssA2;
    const float*  __restrict__ ssBs   = S.ssB2;
    const double* __restrict__ sufAsc = S.sufA2sc;
    const double* __restrict__ preBsc = S.preB2sc;

    const int r    = threadIdx.x / LPR;
    const int lane = threadIdx.x % LPR;
    const int i    = blockIdx.x * IPB + r;
    const int c4   = lane * 4;

    if (lane == 0) {
        const float s1v = s1[i];
        const float ea  = expf(s1v);
        const float eb  = expf(0.01f * s1v);
        const float target = -s1v;
        int lo = 0, hi = 64;
        while (lo < hi) {
            const int mid = (lo + hi) >> 1;
            if (s2c[mid] < target) lo = mid + 1; else hi = mid;
        }
        const int co = lo;
        int l2, h2;
        if (co == 0) { l2 = 0; h2 = 0; }
        else { l2 = 64 * (co - 1) + 1; h2 = (co == 64) ? NN : 64 * co; }
        while (l2 < h2) {
            const int mid = (l2 + h2) >> 1;
            if (s2s[mid] < target) l2 = mid + 1; else h2 = mid;
        }
        const int k = l2;
        const int q = min(k >> CHLOG, NCHUNK - 1);
        const int p0 = q << CHLOG;
        #pragma unroll
        for (int e = 0; e < CHSZ; e++) {
            const int p = p0 + e;
            sCoef[r][e] = (p >= k) ? ea * A[p] : eb * B[p];
            sOff[r][e]  = perm[p] * C;
        }
        const float tii = s1v + s2[i];
        const float wii = expf(tii >= 0.f ? tii : 0.01f * tii);
        const double denom = (double)ea * sufAsc[k] + (double)eb * preBsc[k] - (double)wii;
        sEa[r] = ea;  sEb[r] = eb;  sWii[r] = wii;  sQ[r] = q;
        sRd[r] = 1.0 / denom;
    }
    __syncthreads();

    const float  ea  = sEa[r];
    const float  eb  = sEb[r];
    const float  wii = sWii[r];
    const double rd  = sRd[r];
    const int    q   = sQ[r];
    const int    sq  = q >> SUPLOG;

    const float4 cA = *(const float4*)(csAs + q * C + c4);
    const float4 sAv= *(const float4*)(ssAs + sq * C + c4);
    const float4 cB = *(const float4*)(csBs + q * C + c4);
    const float4 sBv= *(const float4*)(ssBs + sq * C + c4);

    float a0  = ea * (cA.x + sAv.x) + eb * (cB.x + sBv.x);
    float a1_ = ea * (cA.y + sAv.y) + eb * (cB.y + sBv.y);
    float a2_ = ea * (cA.z + sAv.z) + eb * (cB.z + sBv.z);
    float a3  = ea * (cA.w + sAv.w) + eb * (cB.w + sBv.w);

    #pragma unroll
    for (int e = 0; e < CHSZ; e++) {
        const float cf = sCoef[r][e];
        const float4 w4 = *(const float4*)(Wh + (size_t)sOff[r][e] + c4);
        a0  = fmaf(cf, w4.x, a0);
        a1_ = fmaf(cf, w4.y, a1_);
        a2_ = fmaf(cf, w4.z, a2_);
        a3  = fmaf(cf, w4.w, a3);
    }

    const float4 wd = *(const float4*)(Wh + (size_t)i * C + c4);
    float v0 = (float)((double)(a0  - wii * wd.x) * rd);
    float v1 = (float)((double)(a1_ - wii * wd.y) * rd);
    float v2 = (float)((double)(a2_ - wii * wd.z) * rd);
    float v3 = (float)((double)(a3  - wii * wd.w) * rd);
    if (DO_ELU) {
        v0 = (v0 > 0.f) ? v0 : expm1f(v0);
        v1 = (v1 > 0.f) ? v1 : expm1f(v1);
        v2 = (v2 > 0.f) ? v2 : expm1f(v2);
        v3 = (v3 > 0.f) ? v3 : expm1f(v3);
    }
    *(float4*)(out + (size_t)i * rowStride + c4) = make_float4(v0, v1, v2, v3);
}

// ---------------------------------------------------------------------------
// Kernel 6: ALL of layer-2 prep in one single-block kernel.
// ---------------------------------------------------------------------------
__global__ void __launch_bounds__(1024, 1) k_l2prep()
{
    __shared__ float key[NN];
    __shared__ int   sidx[NN];
    const int t = threadIdx.x;

    sort_scan_body(S.s2o, S.s2so, S.s2co, S.permo, S.Ao, S.Bo,
                   S.sufA2sc, S.preB2sc, key, sidx);

    for (int id = t; id < NCHUNK * TT; id += 1024) {
        const int c = id & 15, q = id >> 4;
        const int p0 = q * CHSZ;
        float sa = 0.f, sb = 0.f;
        #pragma unroll
        for (int e = 0; e < CHSZ; e++) {
            const int p = p0 + e;
            const float w = S.Wh2[(size_t)S.permo[p] * TT + c];
            sa = fmaf(S.Ao[p], w, sa);
            sb = fmaf(S.Bo[p], w, sb);
        }
        S.csA2[q * TT + c] = sa;
        S.csB2[q * TT + c] = sb;
    }
    __syncthreads();

    if (t < 512) {
        const int sq = t >> 4, c = t & 15;
        float v[SUPSZ];
        #pragma unroll
        for (int j = 0; j < SUPSZ; j++) v[j] = S.csA2[(sq * SUPSZ + j) * TT + c];
        float run = 0.f;
        #pragma unroll
        for (int j = SUPSZ - 1; j >= 0; j--) { const float tv = v[j]; S.csA2[(sq * SUPSZ + j) * TT + c] = run; run += tv; }
        S.ssA2[sq * TT + c] = run;
    } else {
        const int u = t - 512;
        const int sq = u >> 4, c = u & 15;
        float v[SUPSZ];
        #pragma unroll
        for (int j = 0; j < SUPSZ; j++) v[j] = S.csB2[(sq * SUPSZ + j) * TT + c];
        float run = 0.f;
        #pragma unroll
        for (int j = 0; j < SUPSZ; j++) { const float tv = v[j]; S.csB2[(sq * SUPSZ + j) * TT + c] = run; run += tv; }
        S.ssB2[sq * TT + c] = run;
    }
    __syncthreads();

    if (t < TT) {
        const int c = t;
        float v[NSUPER];
        #pragma unroll
        for (int i = 0; i < NSUPER; i++) v[i] = S.ssA2[i * TT + c];
        float run = 0.f;
        #pragma unroll
        for (int i = NSUPER - 1; i >= 0; i--) { const float tv = v[i]; S.ssA2[i * TT + c] = run; run += tv; }
    } else if (t < 2 * TT) {
        const int c = t - TT;
        float v[NSUPER];
        #pragma unroll
        for (int i = 0; i < NSUPER; i++) v[i] = S.ssB2[i * TT + c];
        float run = 0.f;
        #pragma unroll
        for (int i = 0; i < NSUPER; i++) { const float tv = v[i]; S.ssB2[i * TT + c] = run; run += tv; }
    }
}

// ---------------------------------------------------------------------------
// launch — 6 kernels
// ---------------------------------------------------------------------------
extern "C" void kernel_launch(void* const* d_in, const int* in_sizes, int n_in,
                              void* d_out, int out_size)
{
    const float* x       = (const float*)d_in[0];
    const float* W_heads = (const float*)d_in[3];
    const float* a1h     = (const float*)d_in[4];
    const float* a2h     = (const float*)d_in[5];
    const float* W_out   = (const float*)d_in[6];
    const float* a1o     = (const float*)d_in[7];
    const float* a2o     = (const float*)d_in[8];
    float* out = (float*)d_out;

    // ---- layer 1 ----
    k_gemm1<<<dim3(NN / 64, NH), 256>>>(x, W_heads, a1h, a2h);
    k_sortscan0<<<NH, 1024>>>();
    k_chunksum0<<<dim3(NH, NSUPER), 1024>>>();
    k_combine0_gemm2<<<NN / 4, 256>>>(W_out, a1o, a2o);

    // ---- layer 2 ----
    k_l2prep<<<1, 1024>>>();
    k_combine1<TT, false><<<NN / 64, 256>>>(out, TT);
}